// round 7
// baseline (speedup 1.0000x reference)
#include <cuda_runtime.h>

// ============================================================================
// CustomLinear fused q/k/v projection — f32x2 packed FMA, register-side pack
//   x: (8, 4096, 130) fp32; per token:
//     x1 = x[0:64], s_mid = x[64], x2 = x[65:129], s_last = x[129]
//   q head h<4:  e[65:129] = M_q[h] @ x2 ; e[129] = s_last*bq[h]
//   q head h>=4: e[65]     = s_last*bq[h]
//   k head h<4:  e[65:129] = M_k[h] @ x1 ; e[129] = s_last*bk[h]
//   k head h>=4: e[65]     = s_mid *bk[h]
//   v all h:     e[65:129] = M_v[h] @ x1
//   out = concat(q, k, v), each (8, 4096, 8*130) fp32
// ============================================================================

#define TOK 32   // tokens per CTA
#define TG  8    // tokens per register accumulation group

typedef unsigned long long ull;

// Transposed weights: g_MT[m][j*64 + i] = M_m[i][j], m = 0..3 Mq, 4..7 Mk, 8..15 Mv
__device__ __align__(16) float g_MT[16 * 4096];

__global__ void transpose_kernel(const float* __restrict__ Mq,
                                 const float* __restrict__ Mk,
                                 const float* __restrict__ Mv) {
    int m = blockIdx.x;  // 0..15
    const float* src = (m < 4) ? (Mq + m * 4096)
                     : (m < 8) ? (Mk + (m - 4) * 4096)
                               : (Mv + (m - 8) * 4096);
    float* dst = g_MT + m * 4096;
    for (int idx = threadIdx.x; idx < 4096; idx += blockDim.x) {
        int i = idx >> 6, j = idx & 63;
        dst[j * 64 + i] = src[idx];
    }
}

// packed fp32x2 FMA: d.lo += a.lo*b.lo ; d.hi += a.hi*b.hi   (Blackwell PTX)
__device__ __forceinline__ void fma2(ull& d, ull a, ull b) {
    asm("fma.rn.f32x2 %0, %1, %2, %0;" : "+l"(d) : "l"(a), "l"(b));
}

// pack {v, v} into one 64-bit register (alu pipe; overlaps fma pipe)
__device__ __forceinline__ ull dup2(float v) {
    ull r;
    asm("mov.b64 %0, {%1, %1};" : "=l"(r) : "f"(v));
    return r;
}

__global__ void __launch_bounds__(256, 3) qkv_kernel(
    const float* __restrict__ x,
    const float* __restrict__ Bq,
    const float* __restrict__ Bk,
    float* __restrict__ out)
{
    __shared__ __align__(16) float xsl[TOK * 64];  // per-token 64-float input slice
    __shared__ float2 xs[TOK];                     // {s_mid, s_last}

    const int  tz = blockIdx.y;                 // 0 = q, 1 = k, 2 = v
    const long g0 = (long)blockIdx.x * TOK;     // first global token of this CTA
    const int  slice_off = (tz == 0) ? 65 : 0;  // q reads x2, k/v read x1

    // Stage x slice for TOK tokens (coalesced 64-float runs per token)
    for (int idx = threadIdx.x; idx < TOK * 64; idx += 256) {
        int t = idx >> 6, j = idx & 63;
        xsl[idx] = x[(g0 + t) * 130 + slice_off + j];
    }
    if (threadIdx.x < TOK) {
        int t = threadIdx.x;
        xs[t] = make_float2(x[(g0 + t) * 130 + 64], x[(g0 + t) * 130 + 129]);
    }
    __syncthreads();

    const int w    = threadIdx.x >> 5;
    const int lane = threadIdx.x & 31;
    // out regions: q | k | v, each 8*4096*1040 floats = 17,039,360 float2
    float2* out2 = (float2*)out + (long)tz * 17039360L;

    int h, ngroup, t0_base;
    const float* MT;
    float bh = 0.f, bh4 = 0.f;
    if (tz < 2) {
        h = w >> 1;                       // matvec head 0..3
        int sub = w & 1;
        ngroup = 2;                       // 2 groups of 8 tokens
        t0_base = sub * 16;
        MT = g_MT + ((tz ? 4 : 0) + h) * 4096;
        const float* Bv = tz ? Bk : Bq;
        bh  = Bv[h];
        bh4 = Bv[h + 4];
    } else {
        h = w;                            // v: warp = head, 4 groups of 8 tokens
        ngroup = 4;
        t0_base = 0;
        MT = g_MT + (8 + h) * 4096;
    }

    for (int grp = 0; grp < ngroup; grp++) {
        const int t0 = t0_base + grp * TG;

        // lane computes packed outputs {2*lane, 2*lane+1} for TG tokens
        ull acc[TG];
        #pragma unroll
        for (int t = 0; t < TG; t++) acc[t] = 0ULL;

        #pragma unroll
        for (int jc = 0; jc < 4; jc++) {
            // register-cache M^T chunk: 16 j's x packed output pair (L1-resident)
            ull m[16];
            #pragma unroll
            for (int jj = 0; jj < 16; jj++)
                m[jj] = __ldg((const ull*)(MT + (jc * 16 + jj) * 64) + lane);

            #pragma unroll
            for (int t = 0; t < TG; t++) {
                const float* xr = xsl + (t0 + t) * 64 + jc * 16;
                #pragma unroll
                for (int jj = 0; jj < 16; jj += 4) {
                    float4 xv = *(const float4*)(xr + jj);   // broadcast LDS.128
                    ull p0 = dup2(xv.x), p1 = dup2(xv.y);
                    ull p2 = dup2(xv.z), p3 = dup2(xv.w);
                    fma2(acc[t], m[jj    ], p0);
                    fma2(acc[t], m[jj + 1], p1);
                    fma2(acc[t], m[jj + 2], p2);
                    fma2(acc[t], m[jj + 3], p3);
                }
            }
        }

        // Write the full 130-float head block(s) as aligned float2 pairs.
        // Pair p covers slots (2p, 2p+1); payload lives at slots 65..129, so
        // pair 32+l = {out[2l-1], out[2l]} via shfl_up.
        #pragma unroll
        for (int t = 0; t < TG; t++) {
            long   g     = g0 + t0 + t;
            float2* dst  = out2 + g * 520 + h * 65;
            float  s_mid = xs[t0 + t].x, s_last = xs[t0 + t].y;
            float2 a     = *(float2*)&acc[t];        // a.x = out[2l], a.y = out[2l+1]

            dst[lane] = make_float2(0.f, 0.f);               // slots 0..63 zero

            float prev = __shfl_up_sync(0xffffffffu, a.y, 1);
            if (lane == 0) prev = 0.f;                       // slot 64 zero
            dst[32 + lane] = make_float2(prev, a.x);         // slots 64..127

            float o63 = __shfl_sync(0xffffffffu, a.y, 31);
            if (lane == 0) {
                float sc = (tz == 2) ? 0.f : s_last * bh;    // slot 129
                dst[64] = make_float2(o63, sc);              // slots 128,129
            }

            if (tz < 2) {
                // companion scalar-only head h+4: all zero except slot 65
                float2* dst2 = out2 + g * 520 + (h + 4) * 65;
                float sc2 = (tz == 0 ? s_last : s_mid) * bh4;
                dst2[lane] = make_float2(0.f, 0.f);
                dst2[32 + lane] = make_float2(0.f, (lane == 0) ? sc2 : 0.f);
                if (lane == 0) dst2[64] = make_float2(0.f, 0.f);
            }
        }
    }
}

extern "C" void kernel_launch(void* const* d_in, const int* in_sizes, int n_in,
                              void* d_out, int out_size) {
    const float* x  = (const float*)d_in[0];
    const float* Mq = (const float*)d_in[1];
    const float* Bq = (const float*)d_in[2];
    const float* Mk = (const float*)d_in[3];
    const float* Bk = (const float*)d_in[4];
    const float* Mv = (const float*)d_in[5];
    float* out = (float*)d_out;

    const int tokens = in_sizes[0] / 130;       // B*N = 32768
    transpose_kernel<<<16, 256>>>(Mq, Mk, Mv);
    dim3 grid(tokens / TOK, 3);
    qkv_kernel<<<grid, 256>>>(x, Bq, Bk, out);
}

// round 8
// speedup vs baseline: 1.2331x; 1.2331x over previous
#include <cuda_runtime.h>
#include <cuda_bf16.h>
#include <cstdint>

typedef unsigned int u32;

// ============================================================================
// CustomLinear fused q/k/v — mma.sync bf16 hi/lo split, global-direct fragments
//   Prep: W and X split to bf16 hi/lo in k-interleaved layout (one LDG.64 per
//         fragment operand pair), plus per-token scalar pairs.
//   Main: grid (tokens/64, 8 GEMMs); no smem, no syncs; warp = 16 feat x 64 tok.
//   k-interleave within a 16-k chunk: order [0,1,8,9, 2,3,10,11, 4,5,12,13, 6,7,14,15]
//     -> pos(kk) = ((kk&7)>>1)*4 + (kk>>3)*2 + (kk&1)
// ============================================================================

#define REGION 34078720L           // 8*4096*1040 floats per q/k/v region
#define NTOK   32768

__device__ __align__(16) __nv_bfloat16 g_Wh[8 * 8192];
__device__ __align__(16) __nv_bfloat16 g_Wl[8 * 8192];
__device__ __align__(16) __nv_bfloat16 g_X[4][NTOK * 64];   // 0 x1h 1 x1l 2 x2h 3 x2l
__device__ __align__(16) float2 g_S[NTOK];                  // {s_mid, s_last}

__device__ __forceinline__ int kpos(int kk) {               // kk in 0..15
    return (((kk & 7) >> 1) << 2) + ((kk >> 3) << 1) + (kk & 1);
}

__device__ __forceinline__ void mma_bf16(float* c,
                                         u32 a0, u32 a1, u32 a2, u32 a3,
                                         u32 b0, u32 b1) {
    asm volatile(
        "mma.sync.aligned.m16n8k16.row.col.f32.bf16.bf16.f32 "
        "{%0,%1,%2,%3}, {%4,%5,%6,%7}, {%8,%9}, {%0,%1,%2,%3};"
        : "+f"(c[0]), "+f"(c[1]), "+f"(c[2]), "+f"(c[3])
        : "r"(a0), "r"(a1), "r"(a2), "r"(a3), "r"(b0), "r"(b1));
}

// ---- prep W: 8 packed GEMMs, A[f][k] hi/lo, interleaved ----
__global__ void prep_w(const float* __restrict__ Mq, const float* __restrict__ Mk,
                       const float* __restrict__ Mv) {
    int g = blockIdx.x;
    int r = (g < 2) ? 0 : (g < 4) ? 1 : 2;
    int p = (g < 2) ? g : (g < 4) ? g - 2 : g - 4;
    const float* Mbase = (r == 0) ? Mq : (r == 1) ? Mk : Mv;
    for (int idx = threadIdx.x; idx < 8192; idx += blockDim.x) {
        int f = idx >> 6, k = idx & 63;
        int head = 2 * p + (f >> 6);
        float v = __ldg(&Mbase[head * 4096 + (f & 63) * 64 + k]);
        __nv_bfloat16 h = __float2bfloat16(v);
        __nv_bfloat16 l = __float2bfloat16(v - __bfloat162float(h));
        int st = g * 8192 + f * 64 + (k >> 4) * 16 + kpos(k & 15);
        g_Wh[st] = h;
        g_Wl[st] = l;
    }
}

// ---- prep X: x1/x2 hi/lo interleaved + scalar pairs ----
__global__ void prep_x(const float* __restrict__ x) {
    const int total = NTOK * 64;
    for (int idx = blockIdx.x * blockDim.x + threadIdx.x; idx < total;
         idx += gridDim.x * blockDim.x) {
        int t = idx >> 6, k = idx & 63;
        int st = t * 64 + (k >> 4) * 16 + kpos(k & 15);
        float v1 = __ldg(&x[t * 130 + k]);
        float v2 = __ldg(&x[t * 130 + 65 + k]);
        __nv_bfloat16 h1 = __float2bfloat16(v1);
        __nv_bfloat16 h2 = __float2bfloat16(v2);
        g_X[0][st] = h1;
        g_X[1][st] = __float2bfloat16(v1 - __bfloat162float(h1));
        g_X[2][st] = h2;
        g_X[3][st] = __float2bfloat16(v2 - __bfloat162float(h2));
        if (k == 0)
            g_S[t] = make_float2(__ldg(&x[t * 130 + 64]), __ldg(&x[t * 130 + 129]));
    }
}

// ---- main: warp = 16 feats x 64 tokens, all operands via LDG.64 ----
__global__ void __launch_bounds__(256, 3) qkv_mma_kernel(
    const float* __restrict__ Bq, const float* __restrict__ Bk,
    float* __restrict__ out)
{
    const int tid  = threadIdx.x;
    const int wid  = tid >> 5;
    const int lane = tid & 31;
    const int g_   = lane >> 2;          // fragment group (A row / B token / C row)
    const int t4   = lane & 3;           // fragment thread  (k pair / C col)
    const long tok0 = (long)blockIdx.x * 64;

    const int g = blockIdx.y;                       // packed GEMM id
    const int r = (g < 2) ? 0 : (g < 4) ? 1 : 2;    // q / k / v
    const int p = (g < 2) ? g : (g < 4) ? g - 2 : g - 4;
    const int fb = wid * 16;

    // A pointers: uint2 index = row*16 + kt*4 + t4  (row stride 64 bf16 = 16 uint2)
    const uint2* Ah = (const uint2*)g_Wh + g * 2048 + (fb + g_) * 16 + t4;
    const uint2* Al = (const uint2*)g_Wl + g * 2048 + (fb + g_) * 16 + t4;
    // B pointers: token row = tok0 + nt*8 + g_
    const __nv_bfloat16* xh = (r == 0) ? g_X[2] : g_X[0];
    const __nv_bfloat16* xl = (r == 0) ? g_X[3] : g_X[1];
    const uint2* Bh = (const uint2*)xh + (tok0 + g_) * 16 + t4;
    const uint2* Bl = (const uint2*)xl + (tok0 + g_) * 16 + t4;

    float c[8][4];
    #pragma unroll
    for (int nt = 0; nt < 8; nt++)
        { c[nt][0] = 0.f; c[nt][1] = 0.f; c[nt][2] = 0.f; c[nt][3] = 0.f; }

    #pragma unroll
    for (int kt = 0; kt < 4; kt++) {
        // A fragments: {a0,a2} from row fb+g_, {a1,a3} from row fb+8+g_
        uint2 aH0 = __ldg(Ah + kt * 4);
        uint2 aH1 = __ldg(Ah + 128 + kt * 4);
        uint2 aL0 = __ldg(Al + kt * 4);
        uint2 aL1 = __ldg(Al + 128 + kt * 4);

        #pragma unroll
        for (int nt = 0; nt < 8; nt++) {
            uint2 bH = __ldg(Bh + nt * 128 + kt * 4);   // {b0, b1}
            uint2 bL = __ldg(Bl + nt * 128 + kt * 4);
            mma_bf16(c[nt], aH0.x, aH1.x, aH0.y, aH1.y, bH.x, bH.y);
            mma_bf16(c[nt], aH0.x, aH1.x, aH0.y, aH1.y, bL.x, bL.y);
            mma_bf16(c[nt], aL0.x, aL1.x, aL0.y, aL1.y, bH.x, bH.y);
        }
    }

    // ---- epilogue: payload stores ----
    float* rbase = out + (long)r * REGION;
    {
        const int head = 2 * p + (fb >> 6);
        const int fh   = (fb & 63) + g_;             // feat-in-head for c0/c1
        float* pbase = rbase + head * 130 + 65;
        #pragma unroll
        for (int nt = 0; nt < 8; nt++) {
            long t0 = tok0 + nt * 8 + 2 * t4;
            float* q0 = pbase + t0 * 1040 + fh;
            q0[0]    = c[nt][0];
            q0[1040] = c[nt][1];
            q0[8]    = c[nt][2];
            q0[1048] = c[nt][3];
        }
    }

    // ---- zeros + scalars: warp wid handles tokens [wid*8, wid*8+8) ----
    {
        const int h0 = 2 * p, h1 = 2 * p + 1, e0 = 4 + 2 * p;
        float tb0 = 0.f, tb1 = 0.f, ebA = 0.f, ebB = 0.f;
        if (r < 2) {
            const float* Bv = r ? Bk : Bq;
            tb0 = __ldg(Bv + h0);        tb1 = __ldg(Bv + h1);
            ebA = __ldg(Bv + 4 + 2 * p); ebB = __ldg(Bv + 5 + 2 * p);
        }
        const float2 z2 = make_float2(0.f, 0.f);
        #pragma unroll
        for (int tt = 0; tt < 8; tt++) {
            long tok = tok0 + wid * 8 + tt;
            float* ob = rbase + tok * 1040;
            float2 s = g_S[tok];                     // {s_mid, s_last}

            ((float2*)(ob + h0 * 130))[lane] = z2;   // head h0 slots 0..63
            ((float2*)(ob + h1 * 130))[lane] = z2;   // head h1 slots 0..63

            if (lane == 0) {
                ob[h0 * 130 + 64]  = 0.f;
                ob[h1 * 130 + 64]  = 0.f;
                ob[h0 * 130 + 129] = (r < 2) ? s.y * tb0 : 0.f;
                ob[h1 * 130 + 129] = (r < 2) ? s.y * tb1 : 0.f;
            }

            if (r < 2) {
                // scalar-only heads e0, e0+1: 130 zeros except slot 65
                ((float2*)(ob + e0 * 130))[lane]       = z2;   // 0..63
                ((float2*)(ob + (e0 + 1) * 130))[lane] = z2;
                float sv = (r == 0) ? s.y : s.x;
                float2 vA = (lane == 0) ? make_float2(0.f, sv * ebA) : z2;
                float2 vB = (lane == 0) ? make_float2(0.f, sv * ebB) : z2;
                ((float2*)(ob + e0 * 130 + 64))[lane]       = vA;  // 64..127
                ((float2*)(ob + (e0 + 1) * 130 + 64))[lane] = vB;
                if (lane == 0) {
                    ((float2*)(ob + e0 * 130 + 128))[0]       = z2;  // 128,129
                    ((float2*)(ob + (e0 + 1) * 130 + 128))[0] = z2;
                }
            }
        }
    }
}

extern "C" void kernel_launch(void* const* d_in, const int* in_sizes, int n_in,
                              void* d_out, int out_size) {
    const float* x  = (const float*)d_in[0];
    const float* Mq = (const float*)d_in[1];
    const float* Bq = (const float*)d_in[2];
    const float* Mk = (const float*)d_in[3];
    const float* Bk = (const float*)d_in[4];
    const float* Mv = (const float*)d_in[5];
    float* out = (float*)d_out;

    const int tokens = in_sizes[0] / 130;   // 32768
    prep_w<<<8, 256>>>(Mq, Mk, Mv);
    prep_x<<<256, 256>>>(x);
    dim3 grid(tokens / 64, 8);
    qkv_mma_kernel<<<grid, 256>>>(Bq, Bk, out);
}